// round 15
// baseline (speedup 1.0000x reference)
#include <cuda_runtime.h>
#include <cuda_bf16.h>
#include <cstdint>
#include <math.h>

#define KT    64
#define VV    50000
#define DD    128
#define BOS_T 62
#define EOS_T 63
#define NB    8192
#define LL    126

#define EPS_F __uint_as_float(1u)
#define CORR_F   1363.2920638356958f   // 126 * log(50000)

#define NLB   3125                     // logits blocks (VV / 16)
#define PSTR  3200                     // padded partials stride

// Scratch (no allocation allowed)
__device__ __align__(128) __nv_bfloat16 g_Tb[VV * KT];  // permuted bf16 exp table
__device__ float g_ps[KT * PSTR];                       // partial col sums [k][blk]
__device__ float g_S[KT];                               // per-tag scale V/sum

// ---------------------------------------------------------------------------
// helpers
// ---------------------------------------------------------------------------
__device__ __forceinline__ void fma2(unsigned long long& d,
                                     unsigned long long a,
                                     unsigned long long b) {
    asm("fma.rn.f32x2 %0, %1, %2, %0;" : "+l"(d) : "l"(a), "l"(b));
}
__device__ __forceinline__ float lo64(unsigned long long v) {
    return __uint_as_float((unsigned)(v & 0xffffffffull));
}
__device__ __forceinline__ float hi64(unsigned long long v) {
    return __uint_as_float((unsigned)(v >> 32));
}
__device__ __forceinline__ uint32_t pack_bf2(float l, float h) {
    uint32_t r;
    asm("cvt.rn.bf16x2.f32 %0, %1, %2;" : "=r"(r) : "f"(h), "f"(l));
    return r;
}
__device__ __forceinline__ uint32_t mulbf2(uint32_t a, uint32_t b) {
    uint32_t r;
    asm("mul.bf16x2 %0, %1, %2;" : "=r"(r) : "r"(a), "r"(b));
    return r;
}
__device__ __forceinline__ float blo(uint32_t e) {
    return __uint_as_float(e << 16);
}
__device__ __forceinline__ float bhi(uint32_t e) {
    return __uint_as_float(e & 0xffff0000u);
}

// D[m16,n8] += A[m16,k16] * B[k16,n8], bf16 in, f32 accum
__device__ __forceinline__ void mma16816(float* c, const uint32_t* a,
                                         const uint32_t* b) {
    asm volatile(
        "mma.sync.aligned.m16n8k16.row.col.f32.bf16.bf16.f32 "
        "{%0,%1,%2,%3}, {%4,%5,%6,%7}, {%8,%9}, {%0,%1,%2,%3};"
        : "+f"(c[0]), "+f"(c[1]), "+f"(c[2]), "+f"(c[3])
        : "r"(a[0]), "r"(a[1]), "r"(a[2]), "r"(a[3]), "r"(b[0]), "r"(b[1]));
}

// ---------------------------------------------------------------------------
// Kernel 1: fused logits -> exp -> permuted bf16 table + per-block col sums.
// Block = 256 threads, 16 words. Permuted row layout: u32 slot (t*8+nc) holds
// cols (8nc+2t, 8nc+2t+1); cols 62,63 forced to 0.
// ---------------------------------------------------------------------------
#define WPB 16
#define TB_STRIDE 132

__global__ void __launch_bounds__(256) logits_kernel(const float* __restrict__ ThetaB,
                                                     const float* __restrict__ E) {
    __shared__ __align__(16) float Tbs[KT * TB_STRIDE];
    __shared__ __align__(16) float Es[WPB * DD];
    __shared__ float Ex[WPB][KT];       // exp values for the block's 16 words
    __shared__ float ssum[256];

    int tid = threadIdx.x;
    int wbase = blockIdx.x * WPB;

    for (int idx = tid; idx < KT * DD; idx += 256) {
        int k = idx >> 7, d = idx & 127;
        Tbs[k * TB_STRIDE + d] = ThetaB[idx];
    }
    for (int idx = tid; idx < WPB * DD; idx += 256)
        Es[idx] = E[(size_t)wbase * DD + idx];
    __syncthreads();

    int k  = tid & 63;
    int ws = tid >> 6;
    unsigned long long a0 = 0, a1 = 0, a2 = 0, a3 = 0;
    #pragma unroll 8
    for (int d = 0; d < DD; d += 4) {
        ulonglong2 tb = *reinterpret_cast<const ulonglong2*>(&Tbs[k * TB_STRIDE + d]);
        ulonglong2 e0 = *reinterpret_cast<const ulonglong2*>(&Es[(ws + 0) * DD + d]);
        ulonglong2 e1 = *reinterpret_cast<const ulonglong2*>(&Es[(ws + 4) * DD + d]);
        ulonglong2 e2 = *reinterpret_cast<const ulonglong2*>(&Es[(ws + 8) * DD + d]);
        ulonglong2 e3 = *reinterpret_cast<const ulonglong2*>(&Es[(ws + 12) * DD + d]);
        fma2(a0, tb.x, e0.x); fma2(a0, tb.y, e0.y);
        fma2(a1, tb.x, e1.x); fma2(a1, tb.y, e1.y);
        fma2(a2, tb.x, e2.x); fma2(a2, tb.y, e2.y);
        fma2(a3, tb.x, e3.x); fma2(a3, tb.y, e3.y);
    }
    float e0 = __expf(lo64(a0) + hi64(a0));
    float e1 = __expf(lo64(a1) + hi64(a1));
    float e2 = __expf(lo64(a2) + hi64(a2));
    float e3 = __expf(lo64(a3) + hi64(a3));
    Ex[ws + 0][k]  = e0;
    Ex[ws + 4][k]  = e1;
    Ex[ws + 8][k]  = e2;
    Ex[ws + 12][k] = e3;
    ssum[tid] = e0 + e1 + e2 + e3;
    __syncthreads();

    // per-block column sums (transposed partials: [k][block], coalesced reduce)
    if (ws == 0) {
        float s = ssum[k] + ssum[k + 64] + ssum[k + 128] + ssum[k + 192];
        g_ps[k * PSTR + blockIdx.x] = s;
    }

    // permuted bf16 write: 64 units = 16 words x 4 t-groups
    if (tid < 64) {
        int wloc = tid >> 2, t = tid & 3;
        unsigned u[8];
        #pragma unroll
        for (int nc = 0; nc < 8; nc++) {
            float a = Ex[wloc][8 * nc + 2 * t];
            float b = Ex[wloc][8 * nc + 2 * t + 1];
            if (t == 3 && nc == 7) { a = 0.f; b = 0.f; }   // cols 62,63
            u[nc] = pack_bf2(a, b);
        }
        uint4* dst = reinterpret_cast<uint4*>(g_Tb) + (size_t)(wbase + wloc) * 8 + t * 2;
        dst[0] = make_uint4(u[0], u[1], u[2], u[3]);
        dst[1] = make_uint4(u[4], u[5], u[6], u[7]);
    }
}

// ---------------------------------------------------------------------------
// Kernel 2: reduce partials -> g_S[k] = V / sum_k. One block per tag.
// ---------------------------------------------------------------------------
__global__ void __launch_bounds__(256) scale_kernel() {
    int k = blockIdx.x;
    int tid = threadIdx.x;
    float s = 0.f;
    for (int i = tid; i < NLB; i += 256)
        s += g_ps[k * PSTR + i];
    __shared__ float ss[256];
    ss[tid] = s;
    __syncthreads();
    for (int off = 128; off > 0; off >>= 1) {
        if (tid < off) ss[tid] += ss[tid + off];
        __syncthreads();
    }
    if (tid == 0) g_S[k] = (float)VV / ss[0];
}

// ---------------------------------------------------------------------------
// Kernel 3: mma.sync forward recursion (R9 design), with prep_A inlined and
// the per-tag scale S folded into A's interior columns at Bf-pack time.
// One warp = 16 sentences, register-only recursion.
// ---------------------------------------------------------------------------
__global__ void __launch_bounds__(64) forward_mma_kernel(const int* __restrict__ words,
                                                         const float* __restrict__ WA,
                                                         float* __restrict__ out) {
    __shared__ float As[KT * KT];    // 16 KB transition probs (f32)
    __shared__ float Ssh[KT];

    int tid  = threadIdx.x;
    int warp = tid >> 5;
    int lane = tid & 31;
    int g = lane >> 2;        // row group: owns rows g, g+8
    int t = lane & 3;         // col/k group

    // --- inline prep_A: thread k computes softmax row k of WA into As ---
    {
        int k = tid;
        float m = -INFINITY;
        for (int j = 0; j < KT; j++) {
            float v = WA[k * KT + j];
            if (j == BOS_T) v = -INFINITY;
            As[k * KT + j] = v;
            m = fmaxf(m, v);
        }
        float s = 0.f;
        for (int j = 0; j < KT; j++) {
            float e = (j == BOS_T) ? 0.f : __expf(As[k * KT + j] - m);
            As[k * KT + j] = e;
            s += e;
        }
        float inv = 1.0f / s;
        for (int j = 0; j < KT; j++)
            As[k * KT + j] = As[k * KT + j] * inv + EPS_F;
        Ssh[tid] = g_S[tid];
    }
    __syncthreads();

    int base = (blockIdx.x * 2 + warp) * 16;

    // B fragments of A_hmm (col-major), interior columns scaled by S[n]
    uint32_t Bf[8][4][2];
    #pragma unroll
    for (int nc = 0; nc < 8; nc++) {
        int n = 8 * nc + g;
        float sn = (n < BOS_T) ? Ssh[n] : 1.0f;
        #pragma unroll
        for (int kc = 0; kc < 4; kc++) {
            int k0 = 16 * kc + 2 * t;
            Bf[nc][kc][0] = pack_bf2(As[(k0 + 0) * KT + n] * sn,
                                     As[(k0 + 1) * KT + n] * sn);
            Bf[nc][kc][1] = pack_bf2(As[(k0 + 8) * KT + n] * sn,
                                     As[(k0 + 9) * KT + n] * sn);
        }
    }

    // alpha fragments: one-hot at k=62
    uint32_t af[4][4];
    #pragma unroll
    for (int kc = 0; kc < 4; kc++)
        #pragma unroll
        for (int i = 0; i < 4; i++) af[kc][i] = 0u;
    if (t == 3) {
        af[3][2] = 0x00003F80u;
        af[3][3] = 0x00003F80u;
    }

    const int* wpg = words + (size_t)(base + g) * LL;
    const int* wph = words + (size_t)(base + g + 8) * LL;
    const uint4* Tb4 = reinterpret_cast<const uint4*>(g_Tb);

    uint32_t eg[8], eh[8];
    {
        int wg = wpg[0], wh = wph[0];
        uint4 ga = Tb4[(size_t)wg * 8 + t * 2], gb = Tb4[(size_t)wg * 8 + t * 2 + 1];
        uint4 ha = Tb4[(size_t)wh * 8 + t * 2], hb = Tb4[(size_t)wh * 8 + t * 2 + 1];
        eg[0] = ga.x; eg[1] = ga.y; eg[2] = ga.z; eg[3] = ga.w;
        eg[4] = gb.x; eg[5] = gb.y; eg[6] = gb.z; eg[7] = gb.w;
        eh[0] = ha.x; eh[1] = ha.y; eh[2] = ha.z; eh[3] = ha.w;
        eh[4] = hb.x; eh[5] = hb.y; eh[6] = hb.z; eh[7] = hb.w;
    }
    int wg1 = wpg[1], wh1 = wph[1];

    float lsc0 = 0.f, lsc1 = 0.f;

    for (int step = 0; step < LL; step++) {
        // prefetch next emissions + word after
        uint4 ga = Tb4[(size_t)wg1 * 8 + t * 2], gb = Tb4[(size_t)wg1 * 8 + t * 2 + 1];
        uint4 ha = Tb4[(size_t)wh1 * 8 + t * 2], hb = Tb4[(size_t)wh1 * 8 + t * 2 + 1];
        int nx = (step + 2 < LL) ? step + 2 : 0;
        int wg2 = wpg[nx], wh2 = wph[nx];

        // D = alpha @ A_hmm'
        float c[8][4];
        #pragma unroll
        for (int nc = 0; nc < 8; nc++) {
            c[nc][0] = 0.f; c[nc][1] = 0.f; c[nc][2] = 0.f; c[nc][3] = 0.f;
            #pragma unroll
            for (int kc = 0; kc < 4; kc++)
                mma16816(c[nc], af[kc], Bf[nc][kc]);
        }

        uint32_t og[8], oh[8];
        if ((step & 15) == 15) {
            // rescale path: f32 emission multiply, per-row max, normalize
            float p[8][4];
            float m0 = -1.f, m1 = -1.f;
            #pragma unroll
            for (int nc = 0; nc < 8; nc++) {
                p[nc][0] = c[nc][0] * blo(eg[nc]);
                p[nc][1] = c[nc][1] * bhi(eg[nc]);
                p[nc][2] = c[nc][2] * blo(eh[nc]);
                p[nc][3] = c[nc][3] * bhi(eh[nc]);
                m0 = fmaxf(m0, fmaxf(p[nc][0], p[nc][1]));
                m1 = fmaxf(m1, fmaxf(p[nc][2], p[nc][3]));
            }
            m0 = fmaxf(m0, __shfl_xor_sync(0xffffffffu, m0, 1));
            m0 = fmaxf(m0, __shfl_xor_sync(0xffffffffu, m0, 2));
            m1 = fmaxf(m1, __shfl_xor_sync(0xffffffffu, m1, 1));
            m1 = fmaxf(m1, __shfl_xor_sync(0xffffffffu, m1, 2));
            float r0 = __fdividef(1.0f, m0);
            float r1 = __fdividef(1.0f, m1);
            lsc0 += __logf(m0);
            lsc1 += __logf(m1);
            #pragma unroll
            for (int nc = 0; nc < 8; nc++) {
                og[nc] = pack_bf2(p[nc][0] * r0, p[nc][1] * r0);
                oh[nc] = pack_bf2(p[nc][2] * r1, p[nc][3] * r1);
            }
        } else {
            // fast path: cvt + packed bf16 multiply -> next fragment directly
            #pragma unroll
            for (int nc = 0; nc < 8; nc++) {
                og[nc] = mulbf2(pack_bf2(c[nc][0], c[nc][1]), eg[nc]);
                oh[nc] = mulbf2(pack_bf2(c[nc][2], c[nc][3]), eh[nc]);
            }
        }

        // D n-chunk pair -> next A k-chunk fragment
        #pragma unroll
        for (int kc = 0; kc < 4; kc++) {
            af[kc][0] = og[2 * kc];
            af[kc][1] = oh[2 * kc];
            af[kc][2] = og[2 * kc + 1];
            af[kc][3] = oh[2 * kc + 1];
        }

        eg[0] = ga.x; eg[1] = ga.y; eg[2] = ga.z; eg[3] = ga.w;
        eg[4] = gb.x; eg[5] = gb.y; eg[6] = gb.z; eg[7] = gb.w;
        eh[0] = ha.x; eh[1] = ha.y; eh[2] = ha.z; eh[3] = ha.w;
        eh[4] = hb.x; eh[5] = hb.y; eh[6] = hb.z; eh[7] = hb.w;
        wg1 = wg2; wh1 = wh2;
    }

    // final transition into EOS: n-chunk 7 (col 63 unscaled, lane t==3 c1/c3)
    float cz[4] = {0.f, 0.f, 0.f, 0.f};
    #pragma unroll
    for (int kc = 0; kc < 4; kc++)
        mma16816(cz, af[kc], Bf[7][kc]);

    if (t == 3) {
        out[base + g]     = lsc0 + __logf(cz[1]) - CORR_F;
        out[base + g + 8] = lsc1 + __logf(cz[3]) - CORR_F;
    }
}

// ---------------------------------------------------------------------------
// Launch (3 kernels)
// ---------------------------------------------------------------------------
extern "C" void kernel_launch(void* const* d_in, const int* in_sizes, int n_in,
                              void* d_out, int out_size) {
    const int*   words  = nullptr;
    const float* ThetaB = nullptr;
    const float* WA     = nullptr;
    const float* E      = nullptr;
    for (int i = 0; i < n_in; i++) {
        switch (in_sizes[i]) {
            case NB * LL:  words  = (const int*)d_in[i];   break;
            case KT * DD:  ThetaB = (const float*)d_in[i]; break;
            case KT * KT:  WA     = (const float*)d_in[i]; break;
            case VV * DD:  E      = (const float*)d_in[i]; break;
            default: break;
        }
    }
    float* out = (float*)d_out;

    logits_kernel<<<NLB, 256>>>(ThetaB, E);
    scale_kernel<<<KT, 256>>>();
    forward_mma_kernel<<<NB / 32, 64>>>(words, WA, out);
}